// round 4
// baseline (speedup 1.0000x reference)
#include <cuda_runtime.h>
#include <math.h>
#include <stdint.h>

#define D_MODEL 1024
#define NHEADS  16
#define DK      64
#define BB      2
#define TT      2048
#define MTOT    (BB*TT)   // 4096 rows

// ---------------- scratch (static device arrays; no allocation allowed) ----
__device__ float g_Qr[MTOT*D_MODEL];    // RoPE'd Q
__device__ float g_Kr[MTOT*D_MODEL];    // RoPE'd K
__device__ float g_V [MTOT*D_MODEL];    // pre-RoPE Q == V (reference uses Wq/bq for V!)
__device__ float g_Attn[MTOT*D_MODEL];  // attention output (heads merged)
__device__ float g_cos[TT*32];
__device__ float g_sin[TT*32];

// ---------------- helpers ---------------------------------------------------
__device__ __forceinline__ uint32_t f2tf(float x)
{
    uint32_t u;
    asm("cvt.rna.tf32.f32 %0, %1;" : "=r"(u) : "f"(x));
    return u;
}

__device__ __forceinline__ void mma8(float4& c,
    uint32_t a0, uint32_t a1, uint32_t a2, uint32_t a3,
    uint32_t b0, uint32_t b1)
{
    asm volatile(
        "mma.sync.aligned.m16n8k8.row.col.f32.tf32.tf32.f32 "
        "{%0,%1,%2,%3}, {%4,%5,%6,%7}, {%8,%9}, {%0,%1,%2,%3};\n"
        : "+f"(c.x), "+f"(c.y), "+f"(c.z), "+f"(c.w)
        : "r"(a0), "r"(a1), "r"(a2), "r"(a3), "r"(b0), "r"(b1));
}

// ldmatrix x4: four 8x4-b32 tiles; lane(g,t) of tile j gets element (g,t)
__device__ __forceinline__ void ldsm4(uint32_t& r0, uint32_t& r1,
                                      uint32_t& r2, uint32_t& r3, uint32_t addr)
{
    asm volatile("ldmatrix.sync.aligned.m8n8.x4.shared.b16 {%0,%1,%2,%3}, [%4];"
                 : "=r"(r0), "=r"(r1), "=r"(r2), "=r"(r3) : "r"(addr));
}

__device__ __forceinline__ uint32_t s2u(const void* p)
{
    return (uint32_t)__cvta_generic_to_shared(p);
}

// ---------------- RoPE table ----------------------------------------------
__global__ void rope_table_kernel(const int* __restrict__ pos)
{
    int t = blockIdx.x;
    int i = threadIdx.x;          // 0..31
    double inv = pow(10000.0, -((double)(2*i) / 64.0));
    float ang = (float)pos[t] * (float)inv;
    g_cos[t*32 + i] = cosf(ang);
    g_sin[t*32 + i] = sinf(ang);
}

// ---------------- TF32 mma GEMM core ----------------------------------------
// Y[m,n] = sum_k X[m,k] * W[n,k]; 128x128 tile, 8 warps (2x4), double-buffered
// smem, ldmatrix fragment loads. Epilogue differs per caller.
#define GLD 36                      // smem ld: stride 144B -> conflict-free LDSM
#define GBUF (128*GLD)
#define GEMM_SMEM_BYTES (4*GBUF*4)  // A0,B0,A1,B1

struct GemmAcc { float4 acc[4][4]; };

__device__ __forceinline__ void gemm_core(
    const float* __restrict__ Xp, const float* __restrict__ Wp,
    uint32_t* dsm, GemmAcc& R,
    int srow, int sc4, int wm, int wn, int lane)
{
    uint32_t* A0 = dsm;
    uint32_t* B0 = dsm + GBUF;
    uint32_t* A1 = dsm + 2*GBUF;
    uint32_t* B1 = dsm + 3*GBUF;

    #pragma unroll
    for (int i = 0; i < 4; i++)
        #pragma unroll
        for (int j = 0; j < 4; j++) R.acc[i][j] = make_float4(0.f,0.f,0.f,0.f);

    // lane-derived ldmatrix offsets
    const int ar = lane & 15;            // A row within 16-row tile
    const int ac = (lane >> 4) << 2;     // A col offset (0 or 4)
    const int br = ((lane >> 4) << 3) + (lane & 7);  // B row within 16
    const int bc = ((lane >> 3) & 1) << 2;           // B col offset

    float4 ra[4], rb[4];
    #pragma unroll
    for (int i = 0; i < 4; i++) {
        ra[i] = *(const float4*)(Xp + (size_t)(i*32) * D_MODEL);
        rb[i] = *(const float4*)(Wp + (size_t)(i*32) * D_MODEL);
    }
    #pragma unroll
    for (int i = 0; i < 4; i++) {
        uint32_t* pa = &A0[(srow + i*32)*GLD + sc4];
        pa[0]=f2tf(ra[i].x); pa[1]=f2tf(ra[i].y); pa[2]=f2tf(ra[i].z); pa[3]=f2tf(ra[i].w);
        uint32_t* pb = &B0[(srow + i*32)*GLD + sc4];
        pb[0]=f2tf(rb[i].x); pb[1]=f2tf(rb[i].y); pb[2]=f2tf(rb[i].z); pb[3]=f2tf(rb[i].w);
    }
    __syncthreads();

    for (int k0 = 0; k0 < D_MODEL; k0 += 32) {
        uint32_t* Ac = (k0 & 32) ? A1 : A0;
        uint32_t* Bc = (k0 & 32) ? B1 : B0;
        uint32_t* An = (k0 & 32) ? A0 : A1;
        uint32_t* Bn = (k0 & 32) ? B0 : B1;
        const bool nxt = (k0 + 32) < D_MODEL;
        if (nxt) {
            #pragma unroll
            for (int i = 0; i < 4; i++) {
                ra[i] = *(const float4*)(Xp + k0 + 32 + (size_t)(i*32) * D_MODEL);
                rb[i] = *(const float4*)(Wp + k0 + 32 + (size_t)(i*32) * D_MODEL);
            }
        }
        uint32_t abase = s2u(&Ac[(wm*64 + ar)*GLD + ac]);
        uint32_t bbase = s2u(&Bc[(wn*32 + br)*GLD + bc]);
        #pragma unroll
        for (int ks = 0; ks < 4; ks++) {
            const int kk = ks * 8;
            uint32_t af[4][4];
            #pragma unroll
            for (int mt = 0; mt < 4; mt++)
                ldsm4(af[mt][0], af[mt][1], af[mt][2], af[mt][3],
                      abase + (uint32_t)((mt*16*GLD + kk) * 4));
            #pragma unroll
            for (int ntp = 0; ntp < 2; ntp++) {
                uint32_t b0, b1, b2, b3;
                ldsm4(b0, b1, b2, b3, bbase + (uint32_t)((ntp*16*GLD + kk) * 4));
                #pragma unroll
                for (int mt = 0; mt < 4; mt++) {
                    mma8(R.acc[mt][2*ntp  ], af[mt][0],af[mt][1],af[mt][2],af[mt][3], b0, b1);
                    mma8(R.acc[mt][2*ntp+1], af[mt][0],af[mt][1],af[mt][2],af[mt][3], b2, b3);
                }
            }
        }
        if (nxt) {
            #pragma unroll
            for (int i = 0; i < 4; i++) {
                uint32_t* pa = &An[(srow + i*32)*GLD + sc4];
                pa[0]=f2tf(ra[i].x); pa[1]=f2tf(ra[i].y); pa[2]=f2tf(ra[i].z); pa[3]=f2tf(ra[i].w);
                uint32_t* pb = &Bn[(srow + i*32)*GLD + sc4];
                pb[0]=f2tf(rb[i].x); pb[1]=f2tf(rb[i].y); pb[2]=f2tf(rb[i].z); pb[3]=f2tf(rb[i].w);
            }
            __syncthreads();
        }
    }
}

// ---------------- Q/K projection + RoPE epilogue ----------------------------
__global__ __launch_bounds__(256) void qk_gemm_kernel(
    const float* __restrict__ X,
    const float* __restrict__ Wq, const float* __restrict__ bq,
    const float* __restrict__ Wk, const float* __restrict__ bk)
{
    extern __shared__ uint32_t dsm[];
    const float* W    = blockIdx.z ? Wk : Wq;
    const float* bias = blockIdx.z ? bk : bq;

    const int tid = threadIdx.x, lane = tid & 31, warp = tid >> 5;
    const int wm = warp >> 2, wn = warp & 3;
    const int g = lane >> 2, t = lane & 3;
    const int m0 = blockIdx.y * 128, n0 = blockIdx.x * 128;
    const int srow = tid >> 3, sc4 = (tid & 7) * 4;

    GemmAcc R;
    gemm_core(X + (size_t)(m0 + srow) * D_MODEL + sc4,
              W + (size_t)(n0 + srow) * D_MODEL + sc4,
              dsm, R, srow, sc4, wm, wn, lane);

    float* outR = blockIdx.z ? g_Kr : g_Qr;
    const bool writeV = (blockIdx.z == 0);

    #pragma unroll
    for (int mt = 0; mt < 4; mt++) {
        int r1 = m0 + wm*64 + mt*16 + g;
        int r2 = r1 + 8;
        int t1 = r1 & (TT-1), t2 = r2 & (TT-1);
        #pragma unroll
        for (int nt = 0; nt < 4; nt++) {
            int n = n0 + wn*32 + nt*8 + 2*t;
            float b0v = bias[n], b1v = bias[n+1];
            int fi = (n & 63) >> 1;
            float4 c = R.acc[mt][nt];
            float y1 = c.x + b0v, y2 = c.y + b1v;
            float z1 = c.z + b0v, z2 = c.w + b1v;
            if (writeV) {
                *(float2*)&g_V[(size_t)r1*D_MODEL + n] = make_float2(y1, y2);
                *(float2*)&g_V[(size_t)r2*D_MODEL + n] = make_float2(z1, z2);
            }
            float c1 = g_cos[t1*32+fi], s1 = g_sin[t1*32+fi];
            float c2 = g_cos[t2*32+fi], s2 = g_sin[t2*32+fi];
            *(float2*)&outR[(size_t)r1*D_MODEL + n] =
                make_float2(y1*c1 - y2*s1, y1*s1 + y2*c1);
            *(float2*)&outR[(size_t)r2*D_MODEL + n] =
                make_float2(z1*c2 - z2*s2, z1*s2 + z2*c2);
        }
    }
}

// ---------------- output projection -----------------------------------------
__global__ __launch_bounds__(256) void o_gemm_kernel(
    const float* __restrict__ W, const float* __restrict__ bias,
    float* __restrict__ Y)
{
    extern __shared__ uint32_t dsm[];
    const int tid = threadIdx.x, lane = tid & 31, warp = tid >> 5;
    const int wm = warp >> 2, wn = warp & 3;
    const int g = lane >> 2, t = lane & 3;
    const int m0 = blockIdx.y * 128, n0 = blockIdx.x * 128;
    const int srow = tid >> 3, sc4 = (tid & 7) * 4;

    GemmAcc R;
    gemm_core(g_Attn + (size_t)(m0 + srow) * D_MODEL + sc4,
              W      + (size_t)(n0 + srow) * D_MODEL + sc4,
              dsm, R, srow, sc4, wm, wn, lane);

    #pragma unroll
    for (int mt = 0; mt < 4; mt++) {
        int r1 = m0 + wm*64 + mt*16 + g;
        int r2 = r1 + 8;
        #pragma unroll
        for (int nt = 0; nt < 4; nt++) {
            int n = n0 + wn*32 + nt*8 + 2*t;
            float b0v = bias[n], b1v = bias[n+1];
            float4 c = R.acc[mt][nt];
            *(float2*)&Y[(size_t)r1*D_MODEL + n] = make_float2(c.x + b0v, c.y + b1v);
            *(float2*)&Y[(size_t)r2*D_MODEL + n] = make_float2(c.z + b0v, c.w + b1v);
        }
    }
}

// ---------------- flash attention (TF32 mma + ldmatrix) ---------------------
#define ALD 68   // stride 272B -> conflict-free LDSM
#define ATT_SMEM_BYTES ((64*ALD + 64*ALD + 128*ALD) * 4)   // Ks + Vs + Ss

__global__ __launch_bounds__(256) void attn_kernel(float* __restrict__ O)
{
    extern __shared__ uint32_t sm[];
    uint32_t* Ks = sm;              // [j=64][d..ALD]
    uint32_t* Vs = Ks + 64*ALD;     // [c=64][j..ALD]  (V transposed)
    uint32_t* Ss = Vs + 64*ALD;     // [r=128][c..ALD] (P staged for PV)

    const int tid = threadIdx.x, lane = tid & 31, warp = tid >> 5;
    const int g = lane >> 2, t = lane & 3;
    const int h = blockIdx.y, b = blockIdx.z;
    const int qbase = (gridDim.x - 1 - blockIdx.x) * 128;  // big tiles first
    const size_t base = (size_t)b * TT * D_MODEL + h * DK;
    const float* Qb = g_Qr + base;
    const float* Kb = g_Kr + base;
    const float* Vb = g_V  + base;

    // ldmatrix lane offsets
    const int ar = lane & 15, ac = (lane >> 4) << 2;
    const int br = ((lane >> 4) << 3) + (lane & 7);
    const int bc = ((lane >> 3) & 1) << 2;
    const uint32_t kbase = s2u(&Ks[br*ALD + bc]);
    const uint32_t vbase = s2u(&Vs[br*ALD + bc]);
    const uint32_t sbase = s2u(&Ss[(warp*16 + ar)*ALD + ac]);

    // Q fragments in registers: warp handles rows [warp*16, warp*16+16)
    uint32_t qa[8][4];
    {
        const float* q1 = Qb + (size_t)(qbase + warp*16 + g) * D_MODEL;
        const float* q2 = q1 + (size_t)8 * D_MODEL;
        #pragma unroll
        for (int ks = 0; ks < 8; ks++) {
            qa[ks][0] = f2tf(__ldg(q1 + ks*8 + t));
            qa[ks][1] = f2tf(__ldg(q2 + ks*8 + t));
            qa[ks][2] = f2tf(__ldg(q1 + ks*8 + t + 4));
            qa[ks][3] = f2tf(__ldg(q2 + ks*8 + t + 4));
        }
    }

    float4 oacc[8];
    #pragma unroll
    for (int nt = 0; nt < 8; nt++) oacc[nt] = make_float4(0.f,0.f,0.f,0.f);
    float m0p = -1e30f, m1p = -1e30f, l0 = 0.f, l1 = 0.f;

    const int qi1 = qbase + warp*16 + g;
    const int qi2 = qi1 + 8;
    const int nkv = (qbase + 128) / 64;

    for (int jt = 0; jt < nkv; jt++) {
        const int j0 = jt * 64;
        __syncthreads();   // prior tile's smem reads done
        #pragma unroll
        for (int i = 0; i < 4; i++) {
            int id = tid + i*256;
            int j = id >> 4, d4 = (id & 15) * 4;
            float4 k4 = *(const float4*)&Kb[(size_t)(j0+j)*D_MODEL + d4];
            uint32_t* pk = &Ks[j*ALD + d4];
            pk[0]=f2tf(k4.x); pk[1]=f2tf(k4.y); pk[2]=f2tf(k4.z); pk[3]=f2tf(k4.w);
            float4 v4 = *(const float4*)&Vb[(size_t)(j0+j)*D_MODEL + d4];
            Vs[(d4+0)*ALD + j] = f2tf(v4.x);
            Vs[(d4+1)*ALD + j] = f2tf(v4.y);
            Vs[(d4+2)*ALD + j] = f2tf(v4.z);
            Vs[(d4+3)*ALD + j] = f2tf(v4.w);
        }
        __syncthreads();

        // S = Q @ K^T
        float4 sacc[8];
        #pragma unroll
        for (int nt = 0; nt < 8; nt++) sacc[nt] = make_float4(0.f,0.f,0.f,0.f);
        #pragma unroll
        for (int ks = 0; ks < 8; ks++) {
            #pragma unroll
            for (int ntp = 0; ntp < 4; ntp++) {
                uint32_t b0, b1, b2, b3;
                ldsm4(b0, b1, b2, b3, kbase + (uint32_t)((ntp*16*ALD + ks*8) * 4));
                mma8(sacc[2*ntp  ], qa[ks][0], qa[ks][1], qa[ks][2], qa[ks][3], b0, b1);
                mma8(sacc[2*ntp+1], qa[ks][0], qa[ks][1], qa[ks][2], qa[ks][3], b2, b3);
            }
        }

        // mask + scale + online softmax (registers + shfl)
        float mx0 = -1e30f, mx1 = -1e30f;
        #pragma unroll
        for (int nt = 0; nt < 8; nt++) {
            int cj = j0 + nt*8 + 2*t;
            float4& c = sacc[nt];
            c.x = (cj     <= qi1) ? c.x * 0.125f : -1e30f;
            c.y = (cj + 1 <= qi1) ? c.y * 0.125f : -1e30f;
            c.z = (cj     <= qi2) ? c.z * 0.125f : -1e30f;
            c.w = (cj + 1 <= qi2) ? c.w * 0.125f : -1e30f;
            mx0 = fmaxf(mx0, fmaxf(c.x, c.y));
            mx1 = fmaxf(mx1, fmaxf(c.z, c.w));
        }
        mx0 = fmaxf(mx0, __shfl_xor_sync(0xffffffffu, mx0, 1));
        mx0 = fmaxf(mx0, __shfl_xor_sync(0xffffffffu, mx0, 2));
        mx1 = fmaxf(mx1, __shfl_xor_sync(0xffffffffu, mx1, 1));
        mx1 = fmaxf(mx1, __shfl_xor_sync(0xffffffffu, mx1, 2));

        float mn0 = fmaxf(m0p, mx0), mn1 = fmaxf(m1p, mx1);
        float scl0 = __expf(m0p - mn0), scl1 = __expf(m1p - mn1);
        m0p = mn0; m1p = mn1;

        float ls0 = 0.f, ls1 = 0.f;
        uint32_t* srow1 = &Ss[(warp*16 + g    )*ALD];
        uint32_t* srow2 = &Ss[(warp*16 + g + 8)*ALD];
        #pragma unroll
        for (int nt = 0; nt < 8; nt++) {
            float4 c = sacc[nt];
            float p0 = __expf(c.x - mn0), p1 = __expf(c.y - mn0);
            float p2 = __expf(c.z - mn1), p3 = __expf(c.w - mn1);
            ls0 += p0 + p1; ls1 += p2 + p3;
            int cc = nt*8 + 2*t;
            srow1[cc] = f2tf(p0); srow1[cc+1] = f2tf(p1);
            srow2[cc] = f2tf(p2); srow2[cc+1] = f2tf(p3);
        }
        ls0 += __shfl_xor_sync(0xffffffffu, ls0, 1);
        ls0 += __shfl_xor_sync(0xffffffffu, ls0, 2);
        ls1 += __shfl_xor_sync(0xffffffffu, ls1, 1);
        ls1 += __shfl_xor_sync(0xffffffffu, ls1, 2);
        l0 = l0*scl0 + ls0;
        l1 = l1*scl1 + ls1;

        #pragma unroll
        for (int nt = 0; nt < 8; nt++) {
            oacc[nt].x *= scl0; oacc[nt].y *= scl0;
            oacc[nt].z *= scl1; oacc[nt].w *= scl1;
        }
        __syncwarp();   // P rows warp-private: STS -> LDSM fence

        // O += P @ V
        #pragma unroll
        for (int ks = 0; ks < 8; ks++) {
            uint32_t a0, a1, a2, a3;
            ldsm4(a0, a1, a2, a3, sbase + (uint32_t)(ks*8*4));
            #pragma unroll
            for (int ntp = 0; ntp < 4; ntp++) {
                uint32_t b0, b1, b2, b3;
                ldsm4(b0, b1, b2, b3, vbase + (uint32_t)((ntp*16*ALD + ks*8) * 4));
                mma8(oacc[2*ntp  ], a0, a1, a2, a3, b0, b1);
                mma8(oacc[2*ntp+1], a0, a1, a2, a3, b2, b3);
            }
        }
    }

    // finalize
    float il0 = 1.f / l0, il1 = 1.f / l1;
    const size_t r1off = base + (size_t)qi1 * D_MODEL;
    const size_t r2off = base + (size_t)qi2 * D_MODEL;
    #pragma unroll
    for (int nt = 0; nt < 8; nt++) {
        int col = nt*8 + 2*t;
        *(float2*)&O[r1off + col] = make_float2(oacc[nt].x*il0, oacc[nt].y*il0);
        *(float2*)&O[r2off + col] = make_float2(oacc[nt].z*il1, oacc[nt].w*il1);
    }
}

// ---------------- launch ----------------------------------------------------
extern "C" void kernel_launch(void* const* d_in, const int* in_sizes, int n_in,
                              void* d_out, int out_size)
{
    (void)in_sizes; (void)n_in; (void)out_size;
    const float* x   = (const float*)d_in[0];
    const int*   pos = (const int*)  d_in[1];
    const float* Wq  = (const float*)d_in[2];
    const float* bq  = (const float*)d_in[3];
    const float* Wk  = (const float*)d_in[4];
    const float* bk  = (const float*)d_in[5];
    // d_in[6], d_in[7] (Wv, bv) unused: reference computes V with Wq/bq
    const float* Wo  = (const float*)d_in[8];
    const float* bo  = (const float*)d_in[9];
    float* out = (float*)d_out;

    cudaFuncSetAttribute(qk_gemm_kernel,
                         cudaFuncAttributeMaxDynamicSharedMemorySize,
                         GEMM_SMEM_BYTES);
    cudaFuncSetAttribute(o_gemm_kernel,
                         cudaFuncAttributeMaxDynamicSharedMemorySize,
                         GEMM_SMEM_BYTES);
    cudaFuncSetAttribute(attn_kernel,
                         cudaFuncAttributeMaxDynamicSharedMemorySize,
                         ATT_SMEM_BYTES);

    rope_table_kernel<<<TT, 32>>>(pos);

    dim3 gq(D_MODEL/128, MTOT/128, 2);
    qk_gemm_kernel<<<gq, 256, GEMM_SMEM_BYTES>>>(x, Wq, bq, Wk, bk);

    float* attn_out_sym;
    cudaGetSymbolAddress((void**)&attn_out_sym, g_Attn);
    dim3 ga(TT/128, NHEADS, BB);
    attn_kernel<<<ga, 256, ATT_SMEM_BYTES>>>(attn_out_sym);

    dim3 go(D_MODEL/128, MTOT/128, 1);
    o_gemm_kernel<<<go, 256, GEMM_SMEM_BYTES>>>(Wo, bo, out);
}

// round 6
// speedup vs baseline: 1.0496x; 1.0496x over previous
#include <cuda_runtime.h>
#include <math.h>
#include <stdint.h>

#define D_MODEL 1024
#define NHEADS  16
#define DK      64
#define BB      2
#define TT      2048
#define MTOT    (BB*TT)   // 4096 rows

// ---------------- scratch (static device arrays; no allocation allowed) ----
__device__ float g_Qr[MTOT*D_MODEL];    // RoPE'd Q (tf32-rounded)
__device__ float g_Kr[MTOT*D_MODEL];    // RoPE'd K (tf32-rounded)
__device__ float g_Vt[MTOT*D_MODEL];    // V transposed [b,h,d,t] (tf32-rounded)
__device__ float g_Attn[MTOT*D_MODEL];  // attention output (tf32-rounded)
__device__ float g_Xr[MTOT*D_MODEL];    // input x, tf32-rounded
__device__ float g_Wqr[D_MODEL*D_MODEL];
__device__ float g_Wkr[D_MODEL*D_MODEL];
__device__ float g_Wor[D_MODEL*D_MODEL];
__device__ float g_cos[TT*32];
__device__ float g_sin[TT*32];

// ---------------- helpers ---------------------------------------------------
__device__ __forceinline__ uint32_t f2tf(float x)
{
    uint32_t u;
    asm("cvt.rna.tf32.f32 %0, %1;" : "=r"(u) : "f"(x));
    return u;
}
__device__ __forceinline__ float f2tff(float x) { uint32_t u = f2tf(x); return __uint_as_float(u); }

__device__ __forceinline__ void mma8(float4& c,
    uint32_t a0, uint32_t a1, uint32_t a2, uint32_t a3,
    uint32_t b0, uint32_t b1)
{
    asm volatile(
        "mma.sync.aligned.m16n8k8.row.col.f32.tf32.tf32.f32 "
        "{%0,%1,%2,%3}, {%4,%5,%6,%7}, {%8,%9}, {%0,%1,%2,%3};\n"
        : "+f"(c.x), "+f"(c.y), "+f"(c.z), "+f"(c.w)
        : "r"(a0), "r"(a1), "r"(a2), "r"(a3), "r"(b0), "r"(b1));
}

__device__ __forceinline__ void ldsm4(uint32_t& r0, uint32_t& r1,
                                      uint32_t& r2, uint32_t& r3, uint32_t addr)
{
    asm volatile("ldmatrix.sync.aligned.m8n8.x4.shared.b16 {%0,%1,%2,%3}, [%4];"
                 : "=r"(r0), "=r"(r1), "=r"(r2), "=r"(r3) : "r"(addr));
}

__device__ __forceinline__ uint32_t s2u(const void* p)
{
    return (uint32_t)__cvta_generic_to_shared(p);
}

__device__ __forceinline__ void cpa16(uint32_t dst, const void* src)
{
    asm volatile("cp.async.cg.shared.global [%0], [%1], 16;" :: "r"(dst), "l"(src));
}
#define CP_COMMIT() asm volatile("cp.async.commit_group;" ::: "memory")
#define CP_WAIT0()  asm volatile("cp.async.wait_group 0;" ::: "memory")

// ---------------- prepass: round fp32 -> tf32 values ------------------------
__global__ void round_tf32_kernel(const float4* __restrict__ src,
                                  float4* __restrict__ dst, int n4)
{
    int i = blockIdx.x * blockDim.x + threadIdx.x;
    if (i < n4) {
        float4 v = src[i];
        float4 o;
        o.x = f2tff(v.x); o.y = f2tff(v.y); o.z = f2tff(v.z); o.w = f2tff(v.w);
        dst[i] = o;
    }
}

// ---------------- RoPE table ------------------------------------------------
__global__ void rope_table_kernel(const int* __restrict__ pos)
{
    int t = blockIdx.x;
    int i = threadIdx.x;          // 0..31
    double inv = pow(10000.0, -((double)(2*i) / 64.0));
    float ang = (float)pos[t] * (float)inv;
    g_cos[t*32 + i] = cosf(ang);
    g_sin[t*32 + i] = sinf(ang);
}

// ---------------- TF32 mma GEMM core (cp.async double-buffered) -------------
#define GLD 36                      // smem ld (words): 144B stride, LDSM conflict-free
#define GBUF (128*GLD)
#define GEMM_SMEM_BYTES (4*GBUF*4)  // A0,B0,A1,B1

struct GemmAcc { float4 acc[4][4]; };

__device__ __forceinline__ void gstage(const float* Xp, const float* Wp,
    uint32_t* A, uint32_t* B, int srow, int sc4, int k0)
{
    #pragma unroll
    for (int i = 0; i < 4; i++) {
        cpa16(s2u(&A[(srow + i*32)*GLD + sc4]), Xp + k0 + (size_t)(i*32) * D_MODEL);
        cpa16(s2u(&B[(srow + i*32)*GLD + sc4]), Wp + k0 + (size_t)(i*32) * D_MODEL);
    }
}

// Xp/Wp point at pre-rounded tf32-valued data (row base + col offset applied).
__device__ __forceinline__ void gemm_core(
    const float* __restrict__ Xp, const float* __restrict__ Wp,
    uint32_t* dsm, GemmAcc& R,
    int srow, int sc4, int wm, int wn, int lane)
{
    uint32_t* A0 = dsm;
    uint32_t* B0 = dsm + GBUF;
    uint32_t* A1 = dsm + 2*GBUF;
    uint32_t* B1 = dsm + 3*GBUF;

    #pragma unroll
    for (int i = 0; i < 4; i++)
        #pragma unroll
        for (int j = 0; j < 4; j++) R.acc[i][j] = make_float4(0.f,0.f,0.f,0.f);

    const int ar = lane & 15;
    const int ac = (lane >> 4) << 2;
    const int br = ((lane >> 4) << 3) + (lane & 7);
    const int bc = ((lane >> 3) & 1) << 2;

    gstage(Xp, Wp, A0, B0, srow, sc4, 0);
    CP_COMMIT();

    for (int k0 = 0; k0 < D_MODEL; k0 += 32) {
        CP_WAIT0();
        __syncthreads();   // chunk ready AND all warps done with other buffer
        uint32_t* Ac = (k0 & 32) ? A1 : A0;
        uint32_t* Bc = (k0 & 32) ? B1 : B0;
        if (k0 + 32 < D_MODEL) {
            gstage(Xp, Wp, (k0 & 32) ? A0 : A1, (k0 & 32) ? B0 : B1,
                   srow, sc4, k0 + 32);
            CP_COMMIT();
        }
        uint32_t abase = s2u(&Ac[(wm*64 + ar)*GLD + ac]);
        uint32_t bbase = s2u(&Bc[(wn*32 + br)*GLD + bc]);
        #pragma unroll
        for (int ks = 0; ks < 4; ks++) {
            const int kk = ks * 8;
            uint32_t af[4][4];
            #pragma unroll
            for (int mt = 0; mt < 4; mt++)
                ldsm4(af[mt][0], af[mt][1], af[mt][2], af[mt][3],
                      abase + (uint32_t)((mt*16*GLD + kk) * 4));
            #pragma unroll
            for (int ntp = 0; ntp < 2; ntp++) {
                uint32_t b0, b1, b2, b3;
                ldsm4(b0, b1, b2, b3, bbase + (uint32_t)((ntp*16*GLD + kk) * 4));
                #pragma unroll
                for (int mt = 0; mt < 4; mt++) {
                    mma8(R.acc[mt][2*ntp  ], af[mt][0],af[mt][1],af[mt][2],af[mt][3], b0, b1);
                    mma8(R.acc[mt][2*ntp+1], af[mt][0],af[mt][1],af[mt][2],af[mt][3], b2, b3);
                }
            }
        }
    }
}

// ---------------- Q/K projection + RoPE epilogue ----------------------------
__global__ __launch_bounds__(256) void qk_gemm_kernel(
    const float* __restrict__ bq, const float* __restrict__ bk)
{
    extern __shared__ uint32_t dsm[];
    const float* W    = blockIdx.z ? g_Wkr : g_Wqr;
    const float* bias = blockIdx.z ? bk : bq;

    const int tid = threadIdx.x, lane = tid & 31, warp = tid >> 5;
    const int wm = warp >> 2, wn = warp & 3;
    const int g = lane >> 2, t = lane & 3;
    const int m0 = blockIdx.y * 128, n0 = blockIdx.x * 128;
    const int srow = tid >> 3, sc4 = (tid & 7) * 4;

    GemmAcc R;
    gemm_core(g_Xr + (size_t)(m0 + srow) * D_MODEL + sc4,
              W    + (size_t)(n0 + srow) * D_MODEL + sc4,
              dsm, R, srow, sc4, wm, wn, lane);

    float* outR = blockIdx.z ? g_Kr : g_Qr;
    const bool writeV = (blockIdx.z == 0);

    #pragma unroll
    for (int mt = 0; mt < 4; mt++) {
        int r1 = m0 + wm*64 + mt*16 + g;
        int r2 = r1 + 8;
        int t1 = r1 & (TT-1), t2 = r2 & (TT-1);
        int b1i = r1 >> 11, b2i = r2 >> 11;
        #pragma unroll
        for (int nt = 0; nt < 4; nt++) {
            int n = n0 + wn*32 + nt*8 + 2*t;
            float b0v = bias[n], b1v = bias[n+1];
            int fi = (n & 63) >> 1;
            float4 c = R.acc[mt][nt];
            float y1 = c.x + b0v, y2 = c.y + b1v;
            float z1 = c.z + b0v, z2 = c.w + b1v;
            if (writeV) {
                // transposed layout [b,h,d,t], tf32-rounded
                int h = n >> 6, d = n & 63;
                size_t vb1 = ((size_t)(b1i*NHEADS + h)*DK + d)*TT;
                size_t vb2 = ((size_t)(b2i*NHEADS + h)*DK + d)*TT;
                g_Vt[vb1 + t1]      = f2tff(y1);
                g_Vt[vb1 + TT + t1] = f2tff(y2);
                g_Vt[vb2 + t2]      = f2tff(z1);
                g_Vt[vb2 + TT + t2] = f2tff(z2);
            }
            float c1 = g_cos[t1*32+fi], s1 = g_sin[t1*32+fi];
            float c2 = g_cos[t2*32+fi], s2 = g_sin[t2*32+fi];
            *(float2*)&outR[(size_t)r1*D_MODEL + n] =
                make_float2(f2tff(y1*c1 - y2*s1), f2tff(y1*s1 + y2*c1));
            *(float2*)&outR[(size_t)r2*D_MODEL + n] =
                make_float2(f2tff(z1*c2 - z2*s2), f2tff(z1*s2 + z2*c2));
        }
    }
}

// ---------------- output projection -----------------------------------------
__global__ __launch_bounds__(256) void o_gemm_kernel(
    const float* __restrict__ bias, float* __restrict__ Y)
{
    extern __shared__ uint32_t dsm[];
    const int tid = threadIdx.x, lane = tid & 31, warp = tid >> 5;
    const int wm = warp >> 2, wn = warp & 3;
    const int g = lane >> 2, t = lane & 3;
    const int m0 = blockIdx.y * 128, n0 = blockIdx.x * 128;
    const int srow = tid >> 3, sc4 = (tid & 7) * 4;

    GemmAcc R;
    gemm_core(g_Attn + (size_t)(m0 + srow) * D_MODEL + sc4,
              g_Wor  + (size_t)(n0 + srow) * D_MODEL + sc4,
              dsm, R, srow, sc4, wm, wn, lane);

    #pragma unroll
    for (int mt = 0; mt < 4; mt++) {
        int r1 = m0 + wm*64 + mt*16 + g;
        int r2 = r1 + 8;
        #pragma unroll
        for (int nt = 0; nt < 4; nt++) {
            int n = n0 + wn*32 + nt*8 + 2*t;
            float b0v = bias[n], b1v = bias[n+1];
            float4 c = R.acc[mt][nt];
            *(float2*)&Y[(size_t)r1*D_MODEL + n] = make_float2(c.x + b0v, c.y + b1v);
            *(float2*)&Y[(size_t)r2*D_MODEL + n] = make_float2(c.z + b0v, c.w + b1v);
        }
    }
}

// ---------------- flash attention (cp.async double-buffered) ----------------
#define ALD 68
// smem: Ks[2][64*ALD] + Vs[2][64*ALD] + Ss[128*ALD]
#define ATT_SMEM_BYTES ((4*64*ALD + 128*ALD) * 4)

__global__ __launch_bounds__(256) void attn_kernel(float* __restrict__ O)
{
    extern __shared__ uint32_t sm[];
    uint32_t* KsB[2] = { sm, sm + 64*ALD };
    uint32_t* VsB[2] = { sm + 2*64*ALD, sm + 3*64*ALD };
    uint32_t* Ss = sm + 4*64*ALD;   // [r=128][c..ALD] P staging

    const int tid = threadIdx.x, lane = tid & 31, warp = tid >> 5;
    const int g = lane >> 2, t = lane & 3;
    const int h = blockIdx.y, b = blockIdx.z;
    const int qbase = (gridDim.x - 1 - blockIdx.x) * 128;  // big tiles first
    const size_t base = (size_t)b * TT * D_MODEL + h * DK;
    const float* Qb  = g_Qr + base;
    const float* Kb  = g_Kr + base;
    const float* Vtb = g_Vt + (size_t)(b*NHEADS + h) * DK * TT;

    // staging task: thread covers row srj, 16 floats at sc16 (4 x 16B chunks)
    const int srj  = tid >> 2;           // row 0..63
    const int sc16 = (tid & 3) * 16;     // float offset 0/16/32/48
    const float* ksrc = Kb  + (size_t)srj * D_MODEL + sc16;
    const float* vsrc = Vtb + (size_t)srj * TT + sc16;

    // ldmatrix lane offsets
    const int ar = lane & 15, ac = (lane >> 4) << 2;
    const int br = ((lane >> 4) << 3) + (lane & 7);
    const int bc = ((lane >> 3) & 1) << 2;
    const uint32_t sbase = s2u(&Ss[(warp*16 + ar)*ALD + ac]);

    // Q fragments (g_Qr pre-rounded)
    uint32_t qa[8][4];
    {
        const float* q1 = Qb + (size_t)(qbase + warp*16 + g) * D_MODEL;
        const float* q2 = q1 + (size_t)8 * D_MODEL;
        #pragma unroll
        for (int ks = 0; ks < 8; ks++) {
            qa[ks][0] = __float_as_uint(__ldg(q1 + ks*8 + t));
            qa[ks][1] = __float_as_uint(__ldg(q2 + ks*8 + t));
            qa[ks][2] = __float_as_uint(__ldg(q1 + ks*8 + t + 4));
            qa[ks][3] = __float_as_uint(__ldg(q2 + ks*8 + t + 4));
        }
    }

    float4 oacc[8];
    #pragma unroll
    for (int nt = 0; nt < 8; nt++) oacc[nt] = make_float4(0.f,0.f,0.f,0.f);
    float m0p = -1e30f, m1p = -1e30f, l0 = 0.f, l1 = 0.f;

    const int qi1 = qbase + warp*16 + g;
    const int qi2 = qi1 + 8;
    const int nkv = (qbase + 128) / 64;

    // prologue: stage tile 0 into buffer 0 (full 64x64 tiles: 4 chunks each)
    #pragma unroll
    for (int c = 0; c < 4; c++) {
        cpa16(s2u(&KsB[0][srj*ALD + sc16 + c*4]), ksrc + c*4);
        cpa16(s2u(&VsB[0][srj*ALD + sc16 + c*4]), vsrc + c*4);
    }
    CP_COMMIT();

    for (int jt = 0; jt < nkv; jt++) {
        const int j0 = jt * 64;
        CP_WAIT0();
        __syncthreads();   // tile ready AND all warps done with other buffer
        const int cur = jt & 1;
        if (jt + 1 < nkv) {
            const int nj0 = j0 + 64;
            uint32_t* Kn = KsB[cur ^ 1];
            uint32_t* Vn = VsB[cur ^ 1];
            #pragma unroll
            for (int c = 0; c < 4; c++) {
                cpa16(s2u(&Kn[srj*ALD + sc16 + c*4]),
                      ksrc + (size_t)nj0 * D_MODEL + c*4);
                cpa16(s2u(&Vn[srj*ALD + sc16 + c*4]), vsrc + nj0 + c*4);
            }
            CP_COMMIT();
        }
        const uint32_t kbase = s2u(&KsB[cur][br*ALD + bc]);
        const uint32_t vbase = s2u(&VsB[cur][br*ALD + bc]);

        // S = Q @ K^T
        float4 sacc[8];
        #pragma unroll
        for (int nt = 0; nt < 8; nt++) sacc[nt] = make_float4(0.f,0.f,0.f,0.f);
        #pragma unroll
        for (int ks = 0; ks < 8; ks++) {
            #pragma unroll
            for (int ntp = 0; ntp < 4; ntp++) {
                uint32_t b0, b1, b2, b3;
                ldsm4(b0, b1, b2, b3, kbase + (uint32_t)((ntp*16*ALD + ks*8) * 4));
                mma8(sacc[2*ntp  ], qa[ks][0], qa[ks][1], qa[ks][2], qa[ks][3], b0, b1);
                mma8(sacc[2*ntp+1], qa[ks][0], qa[ks][1], qa[ks][2], qa[ks][3], b2, b3);
            }
        }

        // mask + scale + online softmax (registers + shfl)
        float mx0 = -1e30f, mx1 = -1e30f;
        #pragma unroll
        for (int nt = 0; nt < 8; nt++) {
            int cj = j0 + nt*8 + 2*t;
            float4& c = sacc[nt];
            c.x = (cj     <= qi1) ? c.x * 0.125f : -1e30f;
            c.y = (cj + 1 <= qi1) ? c.y * 0.125f : -1e30f;
            c.z = (cj     <= qi2) ? c.z * 0.125f : -1e30f;
            c.w = (cj + 1 <= qi2) ? c.w * 0.125f : -1e30f;
            mx0 = fmaxf(mx0, fmaxf(c.x, c.y));
            mx1 = fmaxf(mx1, fmaxf(c.z, c.w));
        }
        mx0 = fmaxf(mx0, __shfl_xor_sync(0xffffffffu, mx0, 1));
        mx0 = fmaxf(mx0, __shfl_xor_sync(0xffffffffu, mx0, 2));
        mx1 = fmaxf(mx1, __shfl_xor_sync(0xffffffffu, mx1, 1));
        mx1 = fmaxf(mx1, __shfl_xor_sync(0xffffffffu, mx1, 2));

        float mn0 = fmaxf(m0p, mx0), mn1 = fmaxf(m1p, mx1);
        float scl0 = __expf(m0p - mn0), scl1 = __expf(m1p - mn1);
        m0p = mn0; m1p = mn1;

        float ls0 = 0.f, ls1 = 0.f;
        uint32_t* srow1 = &Ss[(warp*16 + g    )*ALD];
        uint32_t* srow2 = &Ss[(warp*16 + g + 8)*ALD];
        #pragma unroll
        for (int nt = 0; nt < 8; nt++) {
            float4 c = sacc[nt];
            float p0 = __expf(c.x - mn0), p1 = __expf(c.y - mn0);
            float p2 = __expf(c.z - mn1), p3 = __expf(c.w - mn1);
            ls0 += p0 + p1; ls1 += p2 + p3;
            int cc = nt*8 + 2*t;
            srow1[cc] = f2tf(p0); srow1[cc+1] = f2tf(p1);
            srow2[cc] = f2tf(p2); srow2[cc+1] = f2tf(p3);
        }
        ls0 += __shfl_xor_sync(0xffffffffu, ls0, 1);
        ls0 += __shfl_xor_sync(0xffffffffu, ls0, 2);
        ls1 += __shfl_xor_sync(0xffffffffu, ls1, 1);
        ls1 += __shfl_xor_sync(0xffffffffu, ls1, 2);
        l0 = l0*scl0 + ls0;
        l1 = l1*scl1 + ls1;

        #pragma unroll
        for (int nt = 0; nt < 8; nt++) {
            oacc[nt].x *= scl0; oacc[nt].y *= scl0;
            oacc[nt].z *= scl1; oacc[nt].w *= scl1;
        }
        __syncwarp();   // P rows warp-private: STS -> LDSM fence

        // O += P @ V
        #pragma unroll
        for (int ks = 0; ks < 8; ks++) {
            uint32_t a0, a1, a2, a3;
            ldsm4(a0, a1, a2, a3, sbase + (uint32_t)(ks*8*4));
            #pragma unroll
            for (int ntp = 0; ntp < 4; ntp++) {
                uint32_t b0, b1, b2, b3;
                ldsm4(b0, b1, b2, b3, vbase + (uint32_t)((ntp*16*ALD + ks*8) * 4));
                mma8(oacc[2*ntp  ], a0, a1, a2, a3, b0, b1);
                mma8(oacc[2*ntp+1], a0, a1, a2, a3, b2, b3);
            }
        }
    }

    // finalize: write tf32-rounded so o_gemm can pure-copy stage
    float il0 = 1.f / l0, il1 = 1.f / l1;
    const size_t r1off = base + (size_t)qi1 * D_MODEL;
    const size_t r2off = base + (size_t)qi2 * D_MODEL;
    #pragma unroll
    for (int nt = 0; nt < 8; nt++) {
        int col = nt*8 + 2*t;
        *(float2*)&O[r1off + col] =
            make_float2(f2tff(oacc[nt].x*il0), f2tff(oacc[nt].y*il0));
        *(float2*)&O[r2off + col] =
            make_float2(f2tff(oacc[nt].z*il1), f2tff(oacc[nt].w*il1));
    }
}

// ---------------- launch ----------------------------------------------------
extern "C" void kernel_launch(void* const* d_in, const int* in_sizes, int n_in,
                              void* d_out, int out_size)
{
    (void)in_sizes; (void)n_in; (void)out_size;
    const float* x   = (const float*)d_in[0];
    const int*   pos = (const int*)  d_in[1];
    const float* Wq  = (const float*)d_in[2];
    const float* bq  = (const float*)d_in[3];
    const float* Wk  = (const float*)d_in[4];
    const float* bk  = (const float*)d_in[5];
    // d_in[6], d_in[7] (Wv, bv) unused: reference computes V with Wq/bq
    const float* Wo  = (const float*)d_in[8];
    const float* bo  = (const float*)d_in[9];
    float* out = (float*)d_out;

    cudaFuncSetAttribute(qk_gemm_kernel,
                         cudaFuncAttributeMaxDynamicSharedMemorySize, GEMM_SMEM_BYTES);
    cudaFuncSetAttribute(o_gemm_kernel,
                         cudaFuncAttributeMaxDynamicSharedMemorySize, GEMM_SMEM_BYTES);
    cudaFuncSetAttribute(attn_kernel,
                         cudaFuncAttributeMaxDynamicSharedMemorySize, ATT_SMEM_BYTES);

    float *xr, *wqr, *wkr, *wor, *attn_out_sym;
    cudaGetSymbolAddress((void**)&xr,  g_Xr);
    cudaGetSymbolAddress((void**)&wqr, g_Wqr);
    cudaGetSymbolAddress((void**)&wkr, g_Wkr);
    cudaGetSymbolAddress((void**)&wor, g_Wor);
    cudaGetSymbolAddress((void**)&attn_out_sym, g_Attn);

    rope_table_kernel<<<TT, 32>>>(pos);

    const int NX4 = MTOT*D_MODEL/4, NW4 = D_MODEL*D_MODEL/4;
    round_tf32_kernel<<<NX4/256, 256>>>((const float4*)x, (float4*)xr, NX4);
    round_tf32_kernel<<<NW4/256, 256>>>((const float4*)Wq, (float4*)wqr, NW4);
    round_tf32_kernel<<<NW4/256, 256>>>((const float4*)Wk, (float4*)wkr, NW4);
    round_tf32_kernel<<<NW4/256, 256>>>((const float4*)Wo, (float4*)wor, NW4);

    dim3 gq(D_MODEL/128, MTOT/128, 2);
    qk_gemm_kernel<<<gq, 256, GEMM_SMEM_BYTES>>>(bq, bk);

    dim3 ga(TT/128, NHEADS, BB);
    attn_kernel<<<ga, 256, ATT_SMEM_BYTES>>>(attn_out_sym);

    dim3 go(D_MODEL/128, MTOT/128, 1);
    o_gemm_kernel<<<go, 256, GEMM_SMEM_BYTES>>>(bo, out);
}

// round 7
// speedup vs baseline: 1.0883x; 1.0369x over previous
#include <cuda_runtime.h>
#include <math.h>
#include <stdint.h>

#define D_MODEL 1024
#define NHEADS  16
#define DK      64
#define BB      2
#define TT      2048
#define MTOT    (BB*TT)   // 4096 rows

// ---------------- scratch (static device arrays; no allocation allowed) ----
__device__ float g_Qr[MTOT*D_MODEL];    // RoPE'd Q (tf32-rounded)
__device__ float g_Kr[MTOT*D_MODEL];    // RoPE'd K (tf32-rounded)
__device__ float g_Vt[MTOT*D_MODEL];    // V transposed [b,h,d,t] (tf32-rounded)
__device__ float g_Attn[MTOT*D_MODEL];  // attention output (tf32-rounded)
__device__ float g_Xr[MTOT*D_MODEL];    // input x, tf32-rounded
__device__ float g_Wqr[D_MODEL*D_MODEL];
__device__ float g_Wkr[D_MODEL*D_MODEL];
__device__ float g_Wor[D_MODEL*D_MODEL];
__device__ float g_cos[TT*32];
__device__ float g_sin[TT*32];

// ---------------- helpers ---------------------------------------------------
__device__ __forceinline__ uint32_t f2tf(float x)
{
    uint32_t u;
    asm("cvt.rna.tf32.f32 %0, %1;" : "=r"(u) : "f"(x));
    return u;
}
__device__ __forceinline__ float f2tff(float x) { uint32_t u = f2tf(x); return __uint_as_float(u); }

__device__ __forceinline__ void mma8(float4& c,
    uint32_t a0, uint32_t a1, uint32_t a2, uint32_t a3,
    uint32_t b0, uint32_t b1)
{
    asm volatile(
        "mma.sync.aligned.m16n8k8.row.col.f32.tf32.tf32.f32 "
        "{%0,%1,%2,%3}, {%4,%5,%6,%7}, {%8,%9}, {%0,%1,%2,%3};\n"
        : "+f"(c.x), "+f"(c.y), "+f"(c.z), "+f"(c.w)
        : "r"(a0), "r"(a1), "r"(a2), "r"(a3), "r"(b0), "r"(b1));
}

__device__ __forceinline__ void ldsm4(uint32_t& r0, uint32_t& r1,
                                      uint32_t& r2, uint32_t& r3, uint32_t addr)
{
    asm volatile("ldmatrix.sync.aligned.m8n8.x4.shared.b16 {%0,%1,%2,%3}, [%4];"
                 : "=r"(r0), "=r"(r1), "=r"(r2), "=r"(r3) : "r"(addr));
}

__device__ __forceinline__ uint32_t s2u(const void* p)
{
    return (uint32_t)__cvta_generic_to_shared(p);
}

__device__ __forceinline__ void cpa16(uint32_t dst, const void* src)
{
    asm volatile("cp.async.cg.shared.global [%0], [%1], 16;" :: "r"(dst), "l"(src));
}
#define CP_COMMIT() asm volatile("cp.async.commit_group;" ::: "memory")
#define CP_WAIT0()  asm volatile("cp.async.wait_group 0;" ::: "memory")

// ---------------- prepass: round fp32 -> tf32 values ------------------------
__global__ void round_tf32_kernel(const float4* __restrict__ src,
                                  float4* __restrict__ dst, int n4)
{
    int i = blockIdx.x * blockDim.x + threadIdx.x;
    if (i < n4) {
        float4 v = src[i];
        float4 o;
        o.x = f2tff(v.x); o.y = f2tff(v.y); o.z = f2tff(v.z); o.w = f2tff(v.w);
        dst[i] = o;
    }
}

// ---------------- RoPE table ------------------------------------------------
__global__ void rope_table_kernel(const int* __restrict__ pos)
{
    int t = blockIdx.x;
    int i = threadIdx.x;          // 0..31
    double inv = pow(10000.0, -((double)(2*i) / 64.0));
    float ang = (float)pos[t] * (float)inv;
    g_cos[t*32 + i] = cosf(ang);
    g_sin[t*32 + i] = sinf(ang);
}

// ---------------- TF32 mma GEMM core (cp.async double-buffered) -------------
#define GLD 36                      // smem ld (words): 144B stride, LDSM conflict-free
#define GBUF (128*GLD)
#define GEMM_SMEM_BYTES (4*GBUF*4)  // A0,B0,A1,B1

struct GemmAcc { float4 acc[4][4]; };

__device__ __forceinline__ void gstage(const float* Xp, const float* Wp,
    uint32_t* A, uint32_t* B, int srow, int sc4, int k0)
{
    #pragma unroll
    for (int i = 0; i < 4; i++) {
        cpa16(s2u(&A[(srow + i*32)*GLD + sc4]), Xp + k0 + (size_t)(i*32) * D_MODEL);
        cpa16(s2u(&B[(srow + i*32)*GLD + sc4]), Wp + k0 + (size_t)(i*32) * D_MODEL);
    }
}

// Xp/Wp point at pre-rounded tf32-valued data (row base + col offset applied).
__device__ __forceinline__ void gemm_core(
    const float* __restrict__ Xp, const float* __restrict__ Wp,
    uint32_t* dsm, GemmAcc& R,
    int srow, int sc4, int wm, int wn, int lane)
{
    uint32_t* A0 = dsm;
    uint32_t* B0 = dsm + GBUF;
    uint32_t* A1 = dsm + 2*GBUF;
    uint32_t* B1 = dsm + 3*GBUF;

    #pragma unroll
    for (int i = 0; i < 4; i++)
        #pragma unroll
        for (int j = 0; j < 4; j++) R.acc[i][j] = make_float4(0.f,0.f,0.f,0.f);

    const int ar = lane & 15;
    const int ac = (lane >> 4) << 2;
    const int br = ((lane >> 4) << 3) + (lane & 7);
    const int bc = ((lane >> 3) & 1) << 2;

    gstage(Xp, Wp, A0, B0, srow, sc4, 0);
    CP_COMMIT();

    for (int k0 = 0; k0 < D_MODEL; k0 += 32) {
        CP_WAIT0();
        __syncthreads();   // chunk ready AND all warps done with other buffer
        uint32_t* Ac = (k0 & 32) ? A1 : A0;
        uint32_t* Bc = (k0 & 32) ? B1 : B0;
        if (k0 + 32 < D_MODEL) {
            gstage(Xp, Wp, (k0 & 32) ? A0 : A1, (k0 & 32) ? B0 : B1,
                   srow, sc4, k0 + 32);
            CP_COMMIT();
        }
        uint32_t abase = s2u(&Ac[(wm*64 + ar)*GLD + ac]);
        uint32_t bbase = s2u(&Bc[(wn*32 + br)*GLD + bc]);
        #pragma unroll
        for (int ks = 0; ks < 4; ks++) {
            const int kk = ks * 8;
            uint32_t af[4][4];
            #pragma unroll
            for (int mt = 0; mt < 4; mt++)
                ldsm4(af[mt][0], af[mt][1], af[mt][2], af[mt][3],
                      abase + (uint32_t)((mt*16*GLD + kk) * 4));
            #pragma unroll
            for (int ntp = 0; ntp < 2; ntp++) {
                uint32_t b0, b1, b2, b3;
                ldsm4(b0, b1, b2, b3, bbase + (uint32_t)((ntp*16*GLD + kk) * 4));
                #pragma unroll
                for (int mt = 0; mt < 4; mt++) {
                    mma8(R.acc[mt][2*ntp  ], af[mt][0],af[mt][1],af[mt][2],af[mt][3], b0, b1);
                    mma8(R.acc[mt][2*ntp+1], af[mt][0],af[mt][1],af[mt][2],af[mt][3], b2, b3);
                }
            }
        }
    }
}

// ---------------- Q/K projection + RoPE epilogue ----------------------------
__global__ __launch_bounds__(256) void qk_gemm_kernel(
    const float* __restrict__ bq, const float* __restrict__ bk)
{
    extern __shared__ uint32_t dsm[];
    const float* W    = blockIdx.z ? g_Wkr : g_Wqr;
    const float* bias = blockIdx.z ? bk : bq;

    const int tid = threadIdx.x, lane = tid & 31, warp = tid >> 5;
    const int wm = warp >> 2, wn = warp & 3;
    const int g = lane >> 2, t = lane & 3;
    const int m0 = blockIdx.y * 128, n0 = blockIdx.x * 128;
    const int srow = tid >> 3, sc4 = (tid & 7) * 4;

    GemmAcc R;
    gemm_core(g_Xr + (size_t)(m0 + srow) * D_MODEL + sc4,
              W    + (size_t)(n0 + srow) * D_MODEL + sc4,
              dsm, R, srow, sc4, wm, wn, lane);

    float* outR = blockIdx.z ? g_Kr : g_Qr;
    const bool writeV = (blockIdx.z == 0);

    #pragma unroll
    for (int mt = 0; mt < 4; mt++) {
        int r1 = m0 + wm*64 + mt*16 + g;
        int r2 = r1 + 8;
        int t1 = r1 & (TT-1), t2 = r2 & (TT-1);
        int b1i = r1 >> 11, b2i = r2 >> 11;
        #pragma unroll
        for (int nt = 0; nt < 4; nt++) {
            int n = n0 + wn*32 + nt*8 + 2*t;
            float b0v = bias[n], b1v = bias[n+1];
            int fi = (n & 63) >> 1;
            float4 c = R.acc[mt][nt];
            float y1 = c.x + b0v, y2 = c.y + b1v;
            float z1 = c.z + b0v, z2 = c.w + b1v;
            if (writeV) {
                // transposed layout [b,h,d,t], tf32-rounded
                int h = n >> 6, d = n & 63;
                size_t vb1 = ((size_t)(b1i*NHEADS + h)*DK + d)*TT;
                size_t vb2 = ((size_t)(b2i*NHEADS + h)*DK + d)*TT;
                g_Vt[vb1 + t1]      = f2tff(y1);
                g_Vt[vb1 + TT + t1] = f2tff(y2);
                g_Vt[vb2 + t2]      = f2tff(z1);
                g_Vt[vb2 + TT + t2] = f2tff(z2);
            }
            float c1 = g_cos[t1*32+fi], s1 = g_sin[t1*32+fi];
            float c2 = g_cos[t2*32+fi], s2 = g_sin[t2*32+fi];
            *(float2*)&outR[(size_t)r1*D_MODEL + n] =
                make_float2(f2tff(y1*c1 - y2*s1), f2tff(y1*s1 + y2*c1));
            *(float2*)&outR[(size_t)r2*D_MODEL + n] =
                make_float2(f2tff(z1*c2 - z2*s2), f2tff(z1*s2 + z2*c2));
        }
    }
}

// ---------------- output projection -----------------------------------------
__global__ __launch_bounds__(256) void o_gemm_kernel(
    const float* __restrict__ bias, float* __restrict__ Y)
{
    extern __shared__ uint32_t dsm[];
    const int tid = threadIdx.x, lane = tid & 31, warp = tid >> 5;
    const int wm = warp >> 2, wn = warp & 3;
    const int g = lane >> 2, t = lane & 3;
    const int m0 = blockIdx.y * 128, n0 = blockIdx.x * 128;
    const int srow = tid >> 3, sc4 = (tid & 7) * 4;

    GemmAcc R;
    gemm_core(g_Attn + (size_t)(m0 + srow) * D_MODEL + sc4,
              g_Wor  + (size_t)(n0 + srow) * D_MODEL + sc4,
              dsm, R, srow, sc4, wm, wn, lane);

    #pragma unroll
    for (int mt = 0; mt < 4; mt++) {
        int r1 = m0 + wm*64 + mt*16 + g;
        int r2 = r1 + 8;
        #pragma unroll
        for (int nt = 0; nt < 4; nt++) {
            int n = n0 + wn*32 + nt*8 + 2*t;
            float b0v = bias[n], b1v = bias[n+1];
            float4 c = R.acc[mt][nt];
            *(float2*)&Y[(size_t)r1*D_MODEL + n] = make_float2(c.x + b0v, c.y + b1v);
            *(float2*)&Y[(size_t)r2*D_MODEL + n] = make_float2(c.z + b0v, c.w + b1v);
        }
    }
}

// ---------------- flash attention (deferred PV: tensor/softmax overlap) -----
#define ALD 68
// smem: Ks[2][64*ALD] + Vs[2][64*ALD] + Ss[128*ALD]
#define ATT_SMEM_BYTES ((4*64*ALD + 128*ALD) * 4)

__global__ __launch_bounds__(256) void attn_kernel(float* __restrict__ O)
{
    extern __shared__ uint32_t sm[];
    uint32_t* KsB[2] = { sm, sm + 64*ALD };
    uint32_t* VsB[2] = { sm + 2*64*ALD, sm + 3*64*ALD };
    uint32_t* Ss = sm + 4*64*ALD;   // [r=128][c..ALD] P staging (warp-private rows)

    const int tid = threadIdx.x, lane = tid & 31, warp = tid >> 5;
    const int g = lane >> 2, t = lane & 3;
    const int h = blockIdx.y, b = blockIdx.z;
    const int qbase = (gridDim.x - 1 - blockIdx.x) * 128;  // big tiles first
    const size_t base = (size_t)b * TT * D_MODEL + h * DK;
    const float* Qb  = g_Qr + base;
    const float* Kb  = g_Kr + base;
    const float* Vtb = g_Vt + (size_t)(b*NHEADS + h) * DK * TT;

    // staging task: thread covers row srj, 16 floats at sc16 (4 x 16B chunks)
    const int srj  = tid >> 2;           // row 0..63
    const int sc16 = (tid & 3) * 16;     // float offset 0/16/32/48
    const float* ksrc = Kb  + (size_t)srj * D_MODEL + sc16;
    const float* vsrc = Vtb + (size_t)srj * TT + sc16;

    // ldmatrix lane offsets
    const int ar = lane & 15, ac = (lane >> 4) << 2;
    const int br = ((lane >> 4) << 3) + (lane & 7);
    const int bc = ((lane >> 3) & 1) << 2;
    const uint32_t sbase = s2u(&Ss[(warp*16 + ar)*ALD + ac]);

    // Q fragments (g_Qr pre-rounded)
    uint32_t qa[8][4];
    {
        const float* q1 = Qb + (size_t)(qbase + warp*16 + g) * D_MODEL;
        const float* q2 = q1 + (size_t)8 * D_MODEL;
        #pragma unroll
        for (int ks = 0; ks < 8; ks++) {
            qa[ks][0] = __float_as_uint(__ldg(q1 + ks*8 + t));
            qa[ks][1] = __float_as_uint(__ldg(q2 + ks*8 + t));
            qa[ks][2] = __float_as_uint(__ldg(q1 + ks*8 + t + 4));
            qa[ks][3] = __float_as_uint(__ldg(q2 + ks*8 + t + 4));
        }
    }

    float4 oacc[8];
    #pragma unroll
    for (int nt = 0; nt < 8; nt++) oacc[nt] = make_float4(0.f,0.f,0.f,0.f);
    float m0p = -1e30f, m1p = -1e30f, l0 = 0.f, l1 = 0.f;
    float scl0p = 0.f, scl1p = 0.f;   // scl from previous tile's softmax

    const int qi1 = qbase + warp*16 + g;
    const int qi2 = qi1 + 8;
    const int nkv = (qbase + 128) / 64;

    // prologue: stage tile 0 into buffer 0 (full 64x64 tiles: 4 chunks each)
    #pragma unroll
    for (int c = 0; c < 4; c++) {
        cpa16(s2u(&KsB[0][srj*ALD + sc16 + c*4]), ksrc + c*4);
        cpa16(s2u(&VsB[0][srj*ALD + sc16 + c*4]), vsrc + c*4);
    }
    CP_COMMIT();

    for (int jt = 0; jt < nkv; jt++) {
        const int j0 = jt * 64;
        CP_WAIT0();
        __syncthreads();   // K/V(jt) staged; prior-iter V reads finished
        const int cur = jt & 1;
        const int prv = cur ^ 1;

        // ---- S(jt) = Q @ K(jt)^T (tensor) ----
        const uint32_t kbase = s2u(&KsB[cur][br*ALD + bc]);
        float4 sacc[8];
        #pragma unroll
        for (int nt = 0; nt < 8; nt++) sacc[nt] = make_float4(0.f,0.f,0.f,0.f);
        #pragma unroll
        for (int ks = 0; ks < 8; ks++) {
            #pragma unroll
            for (int ntp = 0; ntp < 4; ntp++) {
                uint32_t b0, b1, b2, b3;
                ldsm4(b0, b1, b2, b3, kbase + (uint32_t)((ntp*16*ALD + ks*8) * 4));
                mma8(sacc[2*ntp  ], qa[ks][0], qa[ks][1], qa[ks][2], qa[ks][3], b0, b1);
                mma8(sacc[2*ntp+1], qa[ks][0], qa[ks][1], qa[ks][2], qa[ks][3], b2, b3);
            }
        }

        // ---- deferred PV(jt-1): rescale + mma (tensor; overlaps softmax) ----
        if (jt > 0) {
            #pragma unroll
            for (int nt = 0; nt < 8; nt++) {
                oacc[nt].x *= scl0p; oacc[nt].y *= scl0p;
                oacc[nt].z *= scl1p; oacc[nt].w *= scl1p;
            }
            const uint32_t vbase = s2u(&VsB[prv][br*ALD + bc]);
            #pragma unroll
            for (int ks = 0; ks < 8; ks++) {
                uint32_t a0, a1, a2, a3;
                ldsm4(a0, a1, a2, a3, sbase + (uint32_t)(ks*8*4));
                #pragma unroll
                for (int ntp = 0; ntp < 4; ntp++) {
                    uint32_t b0, b1, b2, b3;
                    ldsm4(b0, b1, b2, b3, vbase + (uint32_t)((ntp*16*ALD + ks*8) * 4));
                    mma8(oacc[2*ntp  ], a0, a1, a2, a3, b0, b1);
                    mma8(oacc[2*ntp+1], a0, a1, a2, a3, b2, b3);
                }
            }
        }
        __syncthreads();   // all warps done reading VsB[prv] before prefetch clobbers it

        // ---- prefetch K/V(jt+1) into the buffer PV just vacated ----
        if (jt + 1 < nkv) {
            const int nj0 = j0 + 64;
            uint32_t* Kn = KsB[prv];
            uint32_t* Vn = VsB[prv];
            #pragma unroll
            for (int c = 0; c < 4; c++) {
                cpa16(s2u(&Kn[srj*ALD + sc16 + c*4]),
                      ksrc + (size_t)nj0 * D_MODEL + c*4);
                cpa16(s2u(&Vn[srj*ALD + sc16 + c*4]), vsrc + nj0 + c*4);
            }
            CP_COMMIT();
        }

        // ---- softmax(jt): mask/scale/max/exp, stage P (MUFU; overlaps PV) ----
        float mx0 = -1e30f, mx1 = -1e30f;
        #pragma unroll
        for (int nt = 0; nt < 8; nt++) {
            int cj = j0 + nt*8 + 2*t;
            float4& c = sacc[nt];
            c.x = (cj     <= qi1) ? c.x * 0.125f : -1e30f;
            c.y = (cj + 1 <= qi1) ? c.y * 0.125f : -1e30f;
            c.z = (cj     <= qi2) ? c.z * 0.125f : -1e30f;
            c.w = (cj + 1 <= qi2) ? c.w * 0.125f : -1e30f;
            mx0 = fmaxf(mx0, fmaxf(c.x, c.y));
            mx1 = fmaxf(mx1, fmaxf(c.z, c.w));
        }
        mx0 = fmaxf(mx0, __shfl_xor_sync(0xffffffffu, mx0, 1));
        mx0 = fmaxf(mx0, __shfl_xor_sync(0xffffffffu, mx0, 2));
        mx1 = fmaxf(mx1, __shfl_xor_sync(0xffffffffu, mx1, 1));
        mx1 = fmaxf(mx1, __shfl_xor_sync(0xffffffffu, mx1, 2));

        float mn0 = fmaxf(m0p, mx0), mn1 = fmaxf(m1p, mx1);
        float scl0 = __expf(m0p - mn0), scl1 = __expf(m1p - mn1);
        m0p = mn0; m1p = mn1;

        __syncwarp();   // PV's cross-lane LDSM of Ss done before overwrite
        float ls0 = 0.f, ls1 = 0.f;
        uint32_t* srow1 = &Ss[(warp*16 + g    )*ALD];
        uint32_t* srow2 = &Ss[(warp*16 + g + 8)*ALD];
        #pragma unroll
        for (int nt = 0; nt < 8; nt++) {
            float4 c = sacc[nt];
            float p0 = __expf(c.x - mn0), p1 = __expf(c.y - mn0);
            float p2 = __expf(c.z - mn1), p3 = __expf(c.w - mn1);
            ls0 += p0 + p1; ls1 += p2 + p3;
            int cc = nt*8 + 2*t;
            srow1[cc] = f2tf(p0); srow1[cc+1] = f2tf(p1);
            srow2[cc] = f2tf(p2); srow2[cc+1] = f2tf(p3);
        }
        ls0 += __shfl_xor_sync(0xffffffffu, ls0, 1);
        ls0 += __shfl_xor_sync(0xffffffffu, ls0, 2);
        ls1 += __shfl_xor_sync(0xffffffffu, ls1, 1);
        ls1 += __shfl_xor_sync(0xffffffffu, ls1, 2);
        l0 = l0*scl0 + ls0;
        l1 = l1*scl1 + ls1;
        scl0p = scl0; scl1p = scl1;
        __syncwarp();   // P(jt) visible to cross-lane LDSM in next iter / epilogue
    }

    // ---- epilogue: final PV(nkv-1) + normalize ----
    {
        const int prv = (nkv - 1) & 1;
        #pragma unroll
        for (int nt = 0; nt < 8; nt++) {
            oacc[nt].x *= scl0p; oacc[nt].y *= scl0p;
            oacc[nt].z *= scl1p; oacc[nt].w *= scl1p;
        }
        const uint32_t vbase = s2u(&VsB[prv][br*ALD + bc]);
        #pragma unroll
        for (int ks = 0; ks < 8; ks++) {
            uint32_t a0, a1, a2, a3;
            ldsm4(a0, a1, a2, a3, sbase + (uint32_t)(ks*8*4));
            #pragma unroll
            for (int ntp = 0; ntp < 4; ntp++) {
                uint32_t b0, b1, b2, b3;
                ldsm4(b0, b1, b2, b3, vbase + (uint32_t)((ntp*16*ALD + ks*8) * 4));
                mma8(oacc[2*ntp  ], a0, a1, a2, a3, b0, b1);
                mma8(oacc[2*ntp+1], a0, a1, a2, a3, b2, b3);
            }
        }
    }

    // finalize: write tf32-rounded so o_gemm can pure-copy stage
    float il0 = 1.f / l0, il1 = 1.f / l1;
    const size_t r1off = base + (size_t)qi1 * D_MODEL;
    const size_t r2off = base + (size_t)qi2 * D_MODEL;
    #pragma unroll
    for (int nt = 0; nt < 8; nt++) {
        int col = nt*8 + 2*t;
        *(float2*)&O[r1off + col] =
            make_float2(f2tff(oacc[nt].x*il0), f2tff(oacc[nt].y*il0));
        *(float2*)&O[r2off + col] =
            make_float2(f2tff(oacc[nt].z*il1), f2tff(oacc[nt].w*il1));
    }
}

// ---------------- launch ----------------------------------------------------
extern "C" void kernel_launch(void* const* d_in, const int* in_sizes, int n_in,
                              void* d_out, int out_size)
{
    (void)in_sizes; (void)n_in; (void)out_size;
    const float* x   = (const float*)d_in[0];
    const int*   pos = (const int*)  d_in[1];
    const float* Wq  = (const float*)d_in[2];
    const float* bq  = (const float*)d_in[3];
    const float* Wk  = (const float*)d_in[4];
    const float* bk  = (const float*)d_in[5];
    // d_in[6], d_in[7] (Wv, bv) unused: reference computes V with Wq/bq
    const float* Wo  = (const float*)d_in[8];
    const float* bo  = (const float*)d_in[9];
    float* out = (float*)d_out;

    cudaFuncSetAttribute(qk_gemm_kernel,
                         cudaFuncAttributeMaxDynamicSharedMemorySize, GEMM_SMEM_BYTES);
    cudaFuncSetAttribute(o_gemm_kernel,
                         cudaFuncAttributeMaxDynamicSharedMemorySize, GEMM_SMEM_BYTES);
    cudaFuncSetAttribute(attn_kernel,
                         cudaFuncAttributeMaxDynamicSharedMemorySize, ATT_SMEM_BYTES);

    float *xr, *wqr, *wkr, *wor, *attn_out_sym;
    cudaGetSymbolAddress((void**)&xr,  g_Xr);
    cudaGetSymbolAddress((void**)&wqr, g_Wqr);
    cudaGetSymbolAddress((void**)&wkr, g_Wkr);
    cudaGetSymbolAddress((void**)&wor, g_Wor);
    cudaGetSymbolAddress((void**)&attn_out_sym, g_Attn);

    rope_table_kernel<<<TT, 32>>>(pos);

    const int NX4 = MTOT*D_MODEL/4, NW4 = D_MODEL*D_MODEL/4;
    round_tf32_kernel<<<NX4/256, 256>>>((const float4*)x, (float4*)xr, NX4);
    round_tf32_kernel<<<NW4/256, 256>>>((const float4*)Wq, (float4*)wqr, NW4);
    round_tf32_kernel<<<NW4/256, 256>>>((const float4*)Wk, (float4*)wkr, NW4);
    round_tf32_kernel<<<NW4/256, 256>>>((const float4*)Wo, (float4*)wor, NW4);

    dim3 gq(D_MODEL/128, MTOT/128, 2);
    qk_gemm_kernel<<<gq, 256, GEMM_SMEM_BYTES>>>(bq, bk);

    dim3 ga(TT/128, NHEADS, BB);
    attn_kernel<<<ga, 256, ATT_SMEM_BYTES>>>(attn_out_sym);

    dim3 go(D_MODEL/128, MTOT/128, 1);
    o_gemm_kernel<<<go, 256, GEMM_SMEM_BYTES>>>(bo, out);
}

// round 9
// speedup vs baseline: 1.7605x; 1.6177x over previous
#include <cuda_runtime.h>
#include <cuda_fp16.h>
#include <math.h>
#include <stdint.h>

#define D_MODEL 1024
#define NHEADS  16
#define DK      64
#define BB      2
#define TT      2048
#define MTOT    (BB*TT)   // 4096 rows

// ---------------- scratch (static device arrays; no allocation allowed) ----
__device__ __half g_Qr[MTOT*D_MODEL];    // RoPE'd Q (fp16)
__device__ __half g_Kr[MTOT*D_MODEL];    // RoPE'd K (fp16)
__device__ __half g_Vt[MTOT*D_MODEL];    // V transposed [b,h,d,t] (fp16)
__device__ __half g_Attn[MTOT*D_MODEL];  // attention output (fp16)
__device__ __half g_Xh[MTOT*D_MODEL];    // input x (fp16)
__device__ __half g_Wqh[D_MODEL*D_MODEL];
__device__ __half g_Wkh[D_MODEL*D_MODEL];
__device__ __half g_Woh[D_MODEL*D_MODEL];
__device__ float  g_cos[TT*32];
__device__ float  g_sin[TT*32];

// ---------------- helpers ---------------------------------------------------
__device__ __forceinline__ void mma16(float4& c,
    uint32_t a0, uint32_t a1, uint32_t a2, uint32_t a3,
    uint32_t b0, uint32_t b1)
{
    asm volatile(
        "mma.sync.aligned.m16n8k16.row.col.f32.f16.f16.f32 "
        "{%0,%1,%2,%3}, {%4,%5,%6,%7}, {%8,%9}, {%0,%1,%2,%3};\n"
        : "+f"(c.x), "+f"(c.y), "+f"(c.z), "+f"(c.w)
        : "r"(a0), "r"(a1), "r"(a2), "r"(a3), "r"(b0), "r"(b1));
}

__device__ __forceinline__ void ldsm4(uint32_t& r0, uint32_t& r1,
                                      uint32_t& r2, uint32_t& r3, uint32_t addr)
{
    asm volatile("ldmatrix.sync.aligned.m8n8.x4.shared.b16 {%0,%1,%2,%3}, [%4];"
                 : "=r"(r0), "=r"(r1), "=r"(r2), "=r"(r3) : "r"(addr));
}

__device__ __forceinline__ uint32_t s2u(const void* p)
{
    return (uint32_t)__cvta_generic_to_shared(p);
}

__device__ __forceinline__ void cpa16(uint32_t dst, const void* src)
{
    asm volatile("cp.async.cg.shared.global [%0], [%1], 16;" :: "r"(dst), "l"(src));
}
#define CP_COMMIT() asm volatile("cp.async.commit_group;" ::: "memory")
#define CP_WAIT0()  asm volatile("cp.async.wait_group 0;" ::: "memory")

// ---------------- prepass: f32 -> f16 ---------------------------------------
__global__ void f2h_kernel(const float4* __restrict__ src,
                           uint4* __restrict__ dst, int n8)
{
    int i = blockIdx.x * blockDim.x + threadIdx.x;
    if (i < n8) {
        float4 a = src[2*i], b = src[2*i+1];
        union { uint4 u; __half2 h[4]; } p;
        p.h[0] = __floats2half2_rn(a.x, a.y);
        p.h[1] = __floats2half2_rn(a.z, a.w);
        p.h[2] = __floats2half2_rn(b.x, b.y);
        p.h[3] = __floats2half2_rn(b.z, b.w);
        dst[i] = p.u;
    }
}

// ---------------- RoPE table ------------------------------------------------
__global__ void rope_table_kernel(const int* __restrict__ pos)
{
    int t = blockIdx.x;
    int i = threadIdx.x;          // 0..31
    double inv = pow(10000.0, -((double)(2*i) / 64.0));
    float ang = (float)pos[t] * (float)inv;
    g_cos[t*32 + i] = cosf(ang);
    g_sin[t*32 + i] = sinf(ang);
}

// ---------------- FP16 mma GEMM core (cp.async double-buffered) -------------
// 128x128 tile, 8 warps (2x4), k-chunk 32. Smem row = 40 halves (80 B stride).
#define GROWB 80                    // bytes per smem row
#define GTILEB (128*GROWB)          // 10240 B per tile buffer
#define GEMM_SMEM_BYTES (4*GTILEB)  // A0,B0,A1,B1 = 40960 B (static)

struct GemmAcc { float4 acc[4][4]; };

__device__ __forceinline__ void gemm_core(
    const __half* __restrict__ Xrow,   // X + (m0+row)*D + hoff (per-thread)
    const __half* __restrict__ Wrow,   // W + (n0+row)*D + hoff
    char* gsm, GemmAcc& R, int tid, int wm, int wn, int lane)
{
    char* A0 = gsm;
    char* B0 = gsm + GTILEB;
    char* A1 = gsm + 2*GTILEB;
    char* B1 = gsm + 3*GTILEB;

    #pragma unroll
    for (int i = 0; i < 4; i++)
        #pragma unroll
        for (int j = 0; j < 4; j++) R.acc[i][j] = make_float4(0.f,0.f,0.f,0.f);

    const int row  = tid >> 1;           // 0..127
    const int hofB = (tid & 1) * 32;     // byte offset within row (0 or 32)

    // ldmatrix lane offsets
    const int arow = lane & 15;
    const int acB  = (lane >> 4) * 16;
    const int brow = ((lane >> 4) << 3) + (lane & 7);
    const int bcB  = ((lane >> 3) & 1) * 16;

    // prologue stage k0=0 into buffer 0
    #pragma unroll
    for (int c = 0; c < 2; c++) {
        cpa16(s2u(A0 + row*GROWB + hofB + c*16), Xrow + c*8);
        cpa16(s2u(B0 + row*GROWB + hofB + c*16), Wrow + c*8);
    }
    CP_COMMIT();

    for (int k0 = 0; k0 < D_MODEL; k0 += 32) {
        CP_WAIT0();
        __syncthreads();
        char* Ac = (k0 & 32) ? A1 : A0;
        char* Bc = (k0 & 32) ? B1 : B0;
        if (k0 + 32 < D_MODEL) {
            char* An = (k0 & 32) ? A0 : A1;
            char* Bn = (k0 & 32) ? B0 : B1;
            #pragma unroll
            for (int c = 0; c < 2; c++) {
                cpa16(s2u(An + row*GROWB + hofB + c*16), Xrow + k0 + 32 + c*8);
                cpa16(s2u(Bn + row*GROWB + hofB + c*16), Wrow + k0 + 32 + c*8);
            }
            CP_COMMIT();
        }
        uint32_t abase = s2u(Ac + (wm*64 + arow)*GROWB + acB);
        uint32_t bbase = s2u(Bc + (wn*32 + brow)*GROWB + bcB);
        #pragma unroll
        for (int ks = 0; ks < 2; ks++) {
            uint32_t af[4][4];
            #pragma unroll
            for (int mt = 0; mt < 4; mt++)
                ldsm4(af[mt][0], af[mt][1], af[mt][2], af[mt][3],
                      abase + (uint32_t)(mt*16*GROWB + ks*32));
            #pragma unroll
            for (int ntp = 0; ntp < 2; ntp++) {
                uint32_t b0, b1, b2, b3;
                ldsm4(b0, b1, b2, b3, bbase + (uint32_t)(ntp*16*GROWB + ks*32));
                #pragma unroll
                for (int mt = 0; mt < 4; mt++) {
                    mma16(R.acc[mt][2*ntp  ], af[mt][0],af[mt][1],af[mt][2],af[mt][3], b0, b1);
                    mma16(R.acc[mt][2*ntp+1], af[mt][0],af[mt][1],af[mt][2],af[mt][3], b2, b3);
                }
            }
        }
    }
}

// ---------------- Q/K projection + RoPE epilogue ----------------------------
__global__ __launch_bounds__(256) void qk_gemm_kernel(
    const float* __restrict__ bq, const float* __restrict__ bk)
{
    __shared__ __align__(16) char gsm[GEMM_SMEM_BYTES];
    const __half* W    = blockIdx.z ? g_Wkh : g_Wqh;
    const float*  bias = blockIdx.z ? bk : bq;

    const int tid = threadIdx.x, lane = tid & 31, warp = tid >> 5;
    const int wm = warp >> 2, wn = warp & 3;
    const int g = lane >> 2, t = lane & 3;
    const int m0 = blockIdx.y * 128, n0 = blockIdx.x * 128;
    const int row = tid >> 1, hoff = (tid & 1) * 16;

    GemmAcc R;
    gemm_core(g_Xh + (size_t)(m0 + row) * D_MODEL + hoff,
              W    + (size_t)(n0 + row) * D_MODEL + hoff,
              gsm, R, tid, wm, wn, lane);

    __half* outR = blockIdx.z ? g_Kr : g_Qr;
    const bool writeV = (blockIdx.z == 0);

    #pragma unroll
    for (int mt = 0; mt < 4; mt++) {
        int r1 = m0 + wm*64 + mt*16 + g;
        int r2 = r1 + 8;
        int t1 = r1 & (TT-1), t2 = r2 & (TT-1);
        int b1i = r1 >> 11, b2i = r2 >> 11;
        #pragma unroll
        for (int nt = 0; nt < 4; nt++) {
            int n = n0 + wn*32 + nt*8 + 2*t;
            float b0v = bias[n], b1v = bias[n+1];
            int fi = (n & 63) >> 1;
            float4 c = R.acc[mt][nt];
            float y1 = c.x + b0v, y2 = c.y + b1v;
            float z1 = c.z + b0v, z2 = c.w + b1v;
            if (writeV) {
                int h = n >> 6, d = n & 63;
                size_t vb1 = ((size_t)(b1i*NHEADS + h)*DK + d)*TT;
                size_t vb2 = ((size_t)(b2i*NHEADS + h)*DK + d)*TT;
                g_Vt[vb1 + t1]      = __float2half_rn(y1);
                g_Vt[vb1 + TT + t1] = __float2half_rn(y2);
                g_Vt[vb2 + t2]      = __float2half_rn(z1);
                g_Vt[vb2 + TT + t2] = __float2half_rn(z2);
            }
            float c1 = g_cos[t1*32+fi], s1 = g_sin[t1*32+fi];
            float c2 = g_cos[t2*32+fi], s2 = g_sin[t2*32+fi];
            *(__half2*)&outR[(size_t)r1*D_MODEL + n] =
                __floats2half2_rn(y1*c1 - y2*s1, y1*s1 + y2*c1);
            *(__half2*)&outR[(size_t)r2*D_MODEL + n] =
                __floats2half2_rn(z1*c2 - z2*s2, z1*s2 + z2*c2);
        }
    }
}

// ---------------- output projection -----------------------------------------
__global__ __launch_bounds__(256) void o_gemm_kernel(
    const float* __restrict__ bias, float* __restrict__ Y)
{
    __shared__ __align__(16) char gsm[GEMM_SMEM_BYTES];
    const int tid = threadIdx.x, lane = tid & 31, warp = tid >> 5;
    const int wm = warp >> 2, wn = warp & 3;
    const int g = lane >> 2, t = lane & 3;
    const int m0 = blockIdx.y * 128, n0 = blockIdx.x * 128;
    const int row = tid >> 1, hoff = (tid & 1) * 16;

    GemmAcc R;
    gemm_core(g_Attn + (size_t)(m0 + row) * D_MODEL + hoff,
              g_Woh  + (size_t)(n0 + row) * D_MODEL + hoff,
              gsm, R, tid, wm, wn, lane);

    #pragma unroll
    for (int mt = 0; mt < 4; mt++) {
        int r1 = m0 + wm*64 + mt*16 + g;
        int r2 = r1 + 8;
        #pragma unroll
        for (int nt = 0; nt < 4; nt++) {
            int n = n0 + wn*32 + nt*8 + 2*t;
            float b0v = bias[n], b1v = bias[n+1];
            float4 c = R.acc[mt][nt];
            *(float2*)&Y[(size_t)r1*D_MODEL + n] = make_float2(c.x + b0v, c.y + b1v);
            *(float2*)&Y[(size_t)r2*D_MODEL + n] = make_float2(c.z + b0v, c.w + b1v);
        }
    }
}

// ---------------- flash attention (fp16, deferred PV) -----------------------
#define AROWB 144                        // bytes per smem row (64 halves + pad)
#define KTILEB (64*AROWB)                // 9216 B
// layout: Ks0, Ks1, Vs0, Vs1, Ss(128 rows)
#define ATT_SMEM_BYTES (4*KTILEB + 128*AROWB)   // 55296 B

__global__ __launch_bounds__(256) void attn_kernel(__half* __restrict__ O)
{
    extern __shared__ char asm_[];
    char* KsB[2] = { asm_, asm_ + KTILEB };
    char* VsB[2] = { asm_ + 2*KTILEB, asm_ + 3*KTILEB };
    char* Ss = asm_ + 4*KTILEB;

    const int tid = threadIdx.x, lane = tid & 31, warp = tid >> 5;
    const int g = lane >> 2, t = lane & 3;
    const int h = blockIdx.y, b = blockIdx.z;
    const int qbase = (gridDim.x - 1 - blockIdx.x) * 128;  // big tiles first
    const size_t base = (size_t)b * TT * D_MODEL + h * DK;
    const __half* Qb  = g_Qr + base;
    const __half* Kb  = g_Kr + base;
    const __half* Vtb = g_Vt + (size_t)(b*NHEADS + h) * DK * TT;

    // staging: thread covers row srj, 16 halves at hoff (2 x 16B chunks)
    const int srj  = tid >> 2;           // row 0..63
    const int hoff = (tid & 3) * 16;     // half offset 0/16/32/48
    const __half* ksrc = Kb  + (size_t)srj * D_MODEL + hoff;
    const __half* vsrc = Vtb + (size_t)srj * TT + hoff;

    // ldmatrix lane offsets
    const int arow = lane & 15, acB = (lane >> 4) * 16;
    const int brow = ((lane >> 4) << 3) + (lane & 7);
    const int bcB  = ((lane >> 3) & 1) * 16;
    const uint32_t sbase = s2u(Ss + (warp*16 + arow)*AROWB + acB);

    // Q fragments in registers: 4 k16-chunks x 4 regs
    uint32_t qa[4][4];
    {
        const __half* q1 = Qb + (size_t)(qbase + warp*16 + g) * D_MODEL;
        const __half* q2 = q1 + (size_t)8 * D_MODEL;
        #pragma unroll
        for (int kc = 0; kc < 4; kc++) {
            qa[kc][0] = *(const uint32_t*)(q1 + kc*16 + 2*t);
            qa[kc][1] = *(const uint32_t*)(q2 + kc*16 + 2*t);
            qa[kc][2] = *(const uint32_t*)(q1 + kc*16 + 2*t + 8);
            qa[kc][3] = *(const uint32_t*)(q2 + kc*16 + 2*t + 8);
        }
    }

    float4 oacc[8];
    #pragma unroll
    for (int nt = 0; nt < 8; nt++) oacc[nt] = make_float4(0.f,0.f,0.f,0.f);
    float m0p = -1e30f, m1p = -1e30f, l0 = 0.f, l1 = 0.f;
    float scl0p = 0.f, scl1p = 0.f;

    const int qi1 = qbase + warp*16 + g;
    const int qi2 = qi1 + 8;
    const int nkv = (qbase + 128) / 64;

    // prologue: stage tile 0
    #pragma unroll
    for (int c = 0; c < 2; c++) {
        cpa16(s2u(KsB[0] + srj*AROWB + hoff*2 + c*16), ksrc + c*8);
        cpa16(s2u(VsB[0] + srj*AROWB + hoff*2 + c*16), vsrc + c*8);
    }
    CP_COMMIT();

    for (int jt = 0; jt < nkv; jt++) {
        const int j0 = jt * 64;
        CP_WAIT0();
        __syncthreads();
        const int cur = jt & 1;
        const int prv = cur ^ 1;

        // ---- S(jt) = Q @ K^T ----
        const uint32_t kbase = s2u(KsB[cur] + brow*AROWB + bcB);
        float4 sacc[8];
        #pragma unroll
        for (int nt = 0; nt < 8; nt++) sacc[nt] = make_float4(0.f,0.f,0.f,0.f);
        #pragma unroll
        for (int kc = 0; kc < 4; kc++) {
            #pragma unroll
            for (int ntp = 0; ntp < 4; ntp++) {
                uint32_t b0, b1, b2, b3;
                ldsm4(b0, b1, b2, b3, kbase + (uint32_t)(ntp*16*AROWB + kc*32));
                mma16(sacc[2*ntp  ], qa[kc][0], qa[kc][1], qa[kc][2], qa[kc][3], b0, b1);
                mma16(sacc[2*ntp+1], qa[kc][0], qa[kc][1], qa[kc][2], qa[kc][3], b2, b3);
            }
        }

        // ---- deferred PV(jt-1) ----
        if (jt > 0) {
            #pragma unroll
            for (int nt = 0; nt < 8; nt++) {
                oacc[nt].x *= scl0p; oacc[nt].y *= scl0p;
                oacc[nt].z *= scl1p; oacc[nt].w *= scl1p;
            }
            const uint32_t vbase = s2u(VsB[prv] + brow*AROWB + bcB);
            #pragma unroll
            for (int kc = 0; kc < 4; kc++) {
                uint32_t a0, a1, a2, a3;
                ldsm4(a0, a1, a2, a3, sbase + (uint32_t)(kc*32));
                #pragma unroll
                for (int ntp = 0; ntp < 4; ntp++) {
                    uint32_t b0, b1, b2, b3;
                    ldsm4(b0, b1, b2, b3, vbase + (uint32_t)(ntp*16*AROWB + kc*32));
                    mma16(oacc[2*ntp  ], a0, a1, a2, a3, b0, b1);
                    mma16(oacc[2*ntp+1], a0, a1, a2, a3, b2, b3);
                }
            }
        }
        __syncthreads();   // done reading VsB[prv] before prefetch clobbers it

        // ---- prefetch K/V(jt+1) ----
        if (jt + 1 < nkv) {
            const int nj0 = j0 + 64;
            #pragma unroll
            for (int c = 0; c < 2; c++) {
                cpa16(s2u(KsB[prv] + srj*AROWB + hoff*2 + c*16),
                      ksrc + (size_t)nj0 * D_MODEL + c*8);
                cpa16(s2u(VsB[prv] + srj*AROWB + hoff*2 + c*16),
                      vsrc + nj0 + c*8);
            }
            CP_COMMIT();
        }

        // ---- softmax(jt) ----
        float mx0 = -1e30f, mx1 = -1e30f;
        #pragma unroll
        for (int nt = 0; nt < 8; nt++) {
            int cj = j0 + nt*8 + 2*t;
            float4& c = sacc[nt];
            c.x = (cj     <= qi1) ? c.x * 0.125f : -1e30f;
            c.y = (cj + 1 <= qi1) ? c.y * 0.125f : -1e30f;
            c.z = (cj     <= qi2) ? c.z * 0.125f : -1e30f;
            c.w = (cj + 1 <= qi2) ? c.w * 0.125f : -1e30f;
            mx0 = fmaxf(mx0, fmaxf(c.x, c.y));
            mx1 = fmaxf(mx1, fmaxf(c.z, c.w));
        }
        mx0 = fmaxf(mx0, __shfl_xor_sync(0xffffffffu, mx0, 1));
        mx0 = fmaxf(mx0, __shfl_xor_sync(0xffffffffu, mx0, 2));
        mx1 = fmaxf(mx1, __shfl_xor_sync(0xffffffffu, mx1, 1));
        mx1 = fmaxf(mx1, __shfl_xor_sync(0xffffffffu, mx1, 2));

        float mn0 = fmaxf(m0p, mx0), mn1 = fmaxf(m1p, mx1);
        float scl0 = __expf(m0p - mn0), scl1 = __expf(m1p - mn1);
        m0p = mn0; m1p = mn1;

        __syncwarp();   // PV's cross-lane LDSM of Ss done before overwrite
        float ls0 = 0.f, ls1 = 0.f;
        __half* srow1 = (__half*)(Ss + (warp*16 + g    )*AROWB);
        __half* srow2 = (__half*)(Ss + (warp*16 + g + 8)*AROWB);
        #pragma unroll
        for (int nt = 0; nt < 8; nt++) {
            float4 c = sacc[nt];
            float p0 = __expf(c.x - mn0), p1 = __expf(c.y - mn0);
            float p2 = __expf(c.z - mn1), p3 = __expf(c.w - mn1);
            ls0 += p0 + p1; ls1 += p2 + p3;
            int cc = nt*8 + 2*t;
            *(__half2*)&srow1[cc] = __floats2half2_rn(p0, p1);
            *(__half2*)&srow2[cc] = __floats2half2_rn(p2, p3);
        }
        ls0 += __shfl_xor_sync(0xffffffffu, ls0, 1);
        ls0 += __shfl_xor_sync(0xffffffffu, ls0, 2);
        ls1 += __shfl_xor_sync(0xffffffffu, ls1, 1);
        ls1 += __shfl_xor_sync(0xffffffffu, ls1, 2);
        l0 = l0*scl0 + ls0;
        l1 = l1*scl1 + ls1;
        scl0p = scl0; scl1p = scl1;
        __syncwarp();   // P(jt) visible to cross-lane LDSM next iter / epilogue
    }

    // ---- epilogue: final PV + normalize ----
    {
        const int prv = (nkv - 1) & 1;
        #pragma unroll
        for (int nt = 0; nt < 8; nt++) {
            oacc[nt].x *= scl0p; oacc[nt].y *= scl0p;
            oacc[nt].z *= scl1p; oacc[nt].w *= scl1p;
        }
        const uint32_t vbase = s2u(VsB[prv] + brow*AROWB + bcB);
        #pragma unroll
        for (int kc = 0; kc < 4; kc++) {
            uint32_t a0, a1, a2, a3;
            ldsm4(a0, a1, a2, a3, sbase + (uint32_t)(kc*32));
            #pragma unroll
            for (int ntp = 0; ntp < 4; ntp++) {
                uint32_t b0, b1, b2, b3;
                ldsm4(b0, b1, b2, b3, vbase + (uint32_t)(ntp*16*AROWB + kc*32));
                mma16(oacc[2*ntp  ], a0, a1, a2, a3, b0, b1);
                mma16(oacc[2*ntp+1], a0, a1, a2, a3, b2, b3);
            }
        }
    }

    float il0 = 1.f / l0, il1 = 1.f / l1;
    const size_t r1off = base + (size_t)qi1 * D_MODEL;
    const size_t r2off = base + (size_t)qi2 * D_MODEL;
    #pragma unroll
    for (int nt = 0; nt < 8; nt++) {
        int col = nt*8 + 2*t;
        *(__half2*)&O[r1off + col] =
            __floats2half2_rn(oacc[nt].x*il0, oacc[nt].y*il0);
        *(__half2*)&O[r2off + col] =
            __floats2half2_rn(oacc[nt].z*il1, oacc[nt].w*il1);
    }
}

// ---------------- launch ----------------------------------------------------
extern "C" void kernel_launch(void* const* d_in, const int* in_sizes, int n_in,
                              void* d_out, int out_size)
{
    (void)in_sizes; (void)n_in; (void)out_size;
    const float* x   = (const float*)d_in[0];
    const int*   pos = (const int*)  d_in[1];
    const float* Wq  = (const float*)d_in[2];
    const float* bq  = (const float*)d_in[3];
    const float* Wk  = (const float*)d_in[4];
    const float* bk  = (const float*)d_in[5];
    // d_in[6], d_in[7] (Wv, bv) unused: reference computes V with Wq/bq
    const float* Wo  = (const float*)d_in[8];
    const float* bo  = (const float*)d_in[9];
    float* out = (float*)d_out;

    cudaFuncSetAttribute(attn_kernel,
                         cudaFuncAttributeMaxDynamicSharedMemorySize, ATT_SMEM_BYTES);

    __half *xh, *wqh, *wkh, *woh, *attn_out_sym;
    cudaGetSymbolAddress((void**)&xh,  g_Xh);
    cudaGetSymbolAddress((void**)&wqh, g_Wqh);
    cudaGetSymbolAddress((void**)&wkh, g_Wkh);
    cudaGetSymbolAddress((void**)&woh, g_Woh);
    cudaGetSymbolAddress((void**)&attn_out_sym, g_Attn);

    rope_table_kernel<<<TT, 32>>>(pos);

    const int NX8 = MTOT*D_MODEL/8, NW8 = D_MODEL*D_MODEL/8;
    f2h_kernel<<<NX8/256, 256>>>((const float4*)x,  (uint4*)xh,  NX8);
    f2h_kernel<<<NW8/256, 256>>>((const float4*)Wq, (uint4*)wqh, NW8);
    f2h_kernel<<<NW8/256, 256>>>((const float4*)Wk, (uint4*)wkh, NW8);
    f2h_kernel<<<NW8/256, 256>>>((const float4*)Wo, (uint4*)woh, NW8);

    dim3 gq(D_MODEL/128, MTOT/128, 2);
    qk_gemm_kernel<<<gq, 256>>>(bq, bk);

    dim3 ga(TT/128, NHEADS, BB);
    attn_kernel<<<ga, 256, ATT_SMEM_BYTES>>>(attn_out_sym);

    dim3 go(D_MODEL/128, MTOT/128, 1);
    o_gemm_kernel<<<go, 256>>>(bo, out);
}